// round 4
// baseline (speedup 1.0000x reference)
#include <cuda_runtime.h>
#include <cstdint>
#include <cstddef>

// Problem dims (fixed by the dataset)
#define T_STEPS 1024
#define BATCH   64
#define HID     512
#define IN_DIM  256
#define OUT_DIM 256

// Recurrence tiling
#define CLUSTER_SZ 8          // CTAs per cluster
#define COLS_PER_CTA 64       // 512 / 8
#define NB_PER_CL 4           // batch rows per cluster (16 clusters * 4 = 64)
#define SWS 516               // padded row stride (floats) for W slice in smem

// Scratch (device globals are the sanctioned scratch mechanism)
__device__ float g_xh[(size_t)BATCH * T_STEPS * HID];   // 128 MiB
__device__ float g_hs[(size_t)BATCH * T_STEPS * HID];   // 128 MiB

// ---------------------------------------------------------------------------
// Classic 128x128x8 fp32 SGEMM with bias:  C[M,N] = A[M,K] @ B[K,N] + bias[N]
// All dims assumed divisible by 128 (M=65536; N=512/256; K=256/512).
// ---------------------------------------------------------------------------
__global__ __launch_bounds__(256)
void sgemm_bias(const float* __restrict__ A, const float* __restrict__ B,
                const float* __restrict__ bias, float* __restrict__ C,
                int M, int N, int K)
{
    __shared__ float As[8][128];
    __shared__ float Bs[8][128];

    const int tid = threadIdx.x;
    const int bm = blockIdx.y;
    const int bn = blockIdx.x;

    const float* Ablk = A + (size_t)bm * 128 * K;
    const float* Bblk = B + (size_t)bn * 128;

    const int arow = tid >> 1;             // 0..127
    const int acol = (tid & 1) * 4;        // 0 or 4
    const int brow = tid >> 5;             // 0..7
    const int bcol = (tid & 31) * 4;       // 0..124

    const int tx = tid & 15;               // 0..15
    const int ty = tid >> 4;               // 0..15

    float acc[8][8];
#pragma unroll
    for (int i = 0; i < 8; i++)
#pragma unroll
        for (int j = 0; j < 8; j++) acc[i][j] = 0.f;

    float ra[8], rb[8];

    for (int k0 = 0; k0 < K; k0 += 8) {
        float4 av = *reinterpret_cast<const float4*>(Ablk + (size_t)arow * K + k0 + acol);
        float4 bv = *reinterpret_cast<const float4*>(Bblk + (size_t)(k0 + brow) * N + bcol);
        As[acol + 0][arow] = av.x;
        As[acol + 1][arow] = av.y;
        As[acol + 2][arow] = av.z;
        As[acol + 3][arow] = av.w;
        *reinterpret_cast<float4*>(&Bs[brow][bcol]) = bv;
        __syncthreads();

#pragma unroll
        for (int k = 0; k < 8; k++) {
            *reinterpret_cast<float4*>(&ra[0]) = *reinterpret_cast<const float4*>(&As[k][ty * 4]);
            *reinterpret_cast<float4*>(&ra[4]) = *reinterpret_cast<const float4*>(&As[k][64 + ty * 4]);
            *reinterpret_cast<float4*>(&rb[0]) = *reinterpret_cast<const float4*>(&Bs[k][tx * 4]);
            *reinterpret_cast<float4*>(&rb[4]) = *reinterpret_cast<const float4*>(&Bs[k][64 + tx * 4]);
#pragma unroll
            for (int i = 0; i < 8; i++)
#pragma unroll
                for (int j = 0; j < 8; j++)
                    acc[i][j] = fmaf(ra[i], rb[j], acc[i][j]);
        }
        __syncthreads();
    }

#pragma unroll
    for (int i = 0; i < 8; i++) {
        int r = (i < 4) ? (ty * 4 + i) : (64 + ty * 4 + (i - 4));
        float* Crow = C + (size_t)(bm * 128 + r) * N + (size_t)bn * 128;
#pragma unroll
        for (int j = 0; j < 8; j++) {
            int cc = (j < 4) ? (tx * 4 + j) : (64 + tx * 4 + (j - 4));
            Crow[cc] = acc[i][j] + bias[bn * 128 + cc];
        }
    }
}

// ---------------------------------------------------------------------------
// Persistent clustered recurrence.
// Grid: 128 CTAs as 16 clusters of 8. Cluster cl handles batches [4cl, 4cl+4).
// CTA rank r holds W_hh[:, r*64:(r+1)*64) in smem (padded, transposed:
// sW[c][k]).  h[2][4][512] double-buffered in every CTA, kept coherent via
// st.shared::cluster broadcast + one cluster.sync per step.
// ---------------------------------------------------------------------------
__device__ __forceinline__ void cluster_sync_all()
{
    asm volatile("barrier.cluster.arrive.aligned;\n\t"
                 "barrier.cluster.wait.aligned;" ::: "memory");
}

extern __shared__ float s_dyn[];

__global__ void __cluster_dims__(CLUSTER_SZ, 1, 1) __launch_bounds__(256, 1)
rnn_recurrence(const float* __restrict__ W_hh)
{
    float* sW = s_dyn;                       // [64][SWS]
    float* sh = s_dyn + COLS_PER_CTA * SWS;  // [2][4][512]

    const int tid  = threadIdx.x;
    const int rank = blockIdx.x & (CLUSTER_SZ - 1);
    const int cl   = blockIdx.x / CLUSTER_SZ;
    const int col0 = rank * COLS_PER_CTA;

    const int nb  = tid >> 6;        // 0..3  batch-within-cluster
    const int c   = tid & 63;        // 0..63 local column
    const int col = col0 + c;        // global hidden column this thread owns
    const int gb  = cl * NB_PER_CL + nb;   // global batch row

    // Load W slice: sW[c][k] = W_hh[k][col0 + c]   (coalesced over c)
    for (int k = tid >> 6; k < HID; k += 4) {
        sW[(tid & 63) * SWS + k] = W_hh[(size_t)k * HID + col0 + (tid & 63)];
    }
    // Zero h buffer 0 (h_{-1} = 0)
    for (int i = tid; i < NB_PER_CL * HID; i += 256) sh[i] = 0.f;
    __syncthreads();
    cluster_sync_all();   // all peers initialized before any remote stores

    uint32_t sh_u32;
    asm("{ .reg .u64 t; cvta.to.shared.u64 t, %1; cvt.u32.u64 %0, t; }"
        : "=r"(sh_u32) : "l"(sh));

    const float* wrow_base = sW + c * SWS;

    int p = 0;
    for (int t = 0; t < T_STEPS; t++) {
        // Prefetch the input-projection term for this step (independent of the
        // dot product below; LDG latency hides under 2K cycles of FFMA).
        const float xh_v = g_xh[((size_t)gb * T_STEPS + t) * HID + col];

        const float4* wrow = reinterpret_cast<const float4*>(wrow_base);
        const float4* hrow = reinterpret_cast<const float4*>(sh + (p * NB_PER_CL + nb) * HID);

        float a0 = 0.f, a1 = 0.f, a2 = 0.f, a3 = 0.f;
#pragma unroll 8
        for (int k = 0; k < HID / 4; k++) {
            float4 w  = wrow[k];
            float4 hv = hrow[k];
            a0 = fmaf(w.x, hv.x, a0);
            a1 = fmaf(w.y, hv.y, a1);
            a2 = fmaf(w.z, hv.z, a2);
            a3 = fmaf(w.w, hv.w, a3);
        }
        const float val = tanhf(a0 + a1 + a2 + a3 + xh_v);

        // Broadcast into h[1-p] of every CTA in the cluster (incl. self).
        const uint32_t dst = sh_u32 +
            (uint32_t)((((1 - p) * NB_PER_CL + nb) * HID + col) * sizeof(float));
#pragma unroll
        for (int r = 0; r < CLUSTER_SZ; r++) {
            uint32_t raddr;
            asm volatile("mapa.shared::cluster.u32 %0, %1, %2;"
                         : "=r"(raddr) : "r"(dst), "r"(r));
            asm volatile("st.shared::cluster.f32 [%0], %1;"
                         :: "r"(raddr), "f"(val) : "memory");
        }

        // Persist h_t for the output GEMM.
        g_hs[((size_t)gb * T_STEPS + t) * HID + col] = val;

        cluster_sync_all();   // release our stores, acquire peers' stores
        p ^= 1;
    }
}

// ---------------------------------------------------------------------------
// Launch
// ---------------------------------------------------------------------------
extern "C" void kernel_launch(void* const* d_in, const int* in_sizes, int n_in,
                              void* d_out, int out_size)
{
    (void)in_sizes; (void)n_in; (void)out_size;
    const float* x    = (const float*)d_in[0];
    const float* W_xh = (const float*)d_in[1];
    const float* W_hh = (const float*)d_in[2];
    const float* b_h  = (const float*)d_in[3];
    const float* W_hy = (const float*)d_in[4];
    const float* b_y  = (const float*)d_in[5];
    float* out = (float*)d_out;

    float *xh_ptr = nullptr, *hs_ptr = nullptr;
    cudaGetSymbolAddress((void**)&xh_ptr, g_xh);
    cudaGetSymbolAddress((void**)&hs_ptr, g_hs);

    const int M = BATCH * T_STEPS;   // 65536

    // 1) xh = x @ W_xh + b_h        [65536,256]@[256,512]
    {
        dim3 grid(HID / 128, M / 128);
        sgemm_bias<<<grid, 256>>>(x, W_xh, b_h, xh_ptr, M, HID, IN_DIM);
    }

    // 2) recurrence (persistent, 16 clusters x 8 CTAs)
    {
        size_t smem = (size_t)(COLS_PER_CTA * SWS + 2 * NB_PER_CL * HID) * sizeof(float);
        cudaFuncSetAttribute(rnn_recurrence,
                             cudaFuncAttributeMaxDynamicSharedMemorySize, (int)smem);
        rnn_recurrence<<<(BATCH / NB_PER_CL) * CLUSTER_SZ, 256, smem>>>(W_hh);
    }

    // 3) out = hs @ W_hy + b_y      [65536,512]@[512,256]
    {
        dim3 grid(OUT_DIM / 128, M / 128);
        sgemm_bias<<<grid, 256>>>(hs_ptr, W_hy, b_y, out, M, OUT_DIM, HID);
    }
}

// round 6
// speedup vs baseline: 1.6420x; 1.6420x over previous
#include <cuda_runtime.h>
#include <cstdint>
#include <cstddef>

// Problem dims (fixed by the dataset)
#define T_STEPS 1024
#define BATCH   64
#define HID     512
#define IN_DIM  256
#define OUT_DIM 256

// Recurrence tiling
#define CLUSTER_SZ 8          // CTAs per cluster
#define COLS_PER_CTA 64       // 512 / 8
#define NB_PER_CL 4           // batch rows per cluster (16 clusters * 4 = 64)
#define SWS 516               // padded row stride (floats) for W slice in smem
#define KQ_GROUPS 8           // k-dimension split per CTA
#define K_PER (HID / KQ_GROUPS)   // 64 k-values per thread

// Scratch (device globals are the sanctioned scratch mechanism)
__device__ float g_xh[(size_t)BATCH * T_STEPS * HID];   // 128 MiB
__device__ float g_hs[(size_t)BATCH * T_STEPS * HID];   // 128 MiB

// ---------------------------------------------------------------------------
// Classic 128x128x8 fp32 SGEMM with bias:  C[M,N] = A[M,K] @ B[K,N] + bias[N]
// ---------------------------------------------------------------------------
__global__ __launch_bounds__(256)
void sgemm_bias(const float* __restrict__ A, const float* __restrict__ B,
                const float* __restrict__ bias, float* __restrict__ C,
                int M, int N, int K)
{
    __shared__ float As[8][128];
    __shared__ float Bs[8][128];

    const int tid = threadIdx.x;
    const int bm = blockIdx.y;
    const int bn = blockIdx.x;

    const float* Ablk = A + (size_t)bm * 128 * K;
    const float* Bblk = B + (size_t)bn * 128;

    const int arow = tid >> 1;
    const int acol = (tid & 1) * 4;
    const int brow = tid >> 5;
    const int bcol = (tid & 31) * 4;

    const int tx = tid & 15;
    const int ty = tid >> 4;

    float acc[8][8];
#pragma unroll
    for (int i = 0; i < 8; i++)
#pragma unroll
        for (int j = 0; j < 8; j++) acc[i][j] = 0.f;

    float ra[8], rb[8];

    for (int k0 = 0; k0 < K; k0 += 8) {
        float4 av = *reinterpret_cast<const float4*>(Ablk + (size_t)arow * K + k0 + acol);
        float4 bv = *reinterpret_cast<const float4*>(Bblk + (size_t)(k0 + brow) * N + bcol);
        As[acol + 0][arow] = av.x;
        As[acol + 1][arow] = av.y;
        As[acol + 2][arow] = av.z;
        As[acol + 3][arow] = av.w;
        *reinterpret_cast<float4*>(&Bs[brow][bcol]) = bv;
        __syncthreads();

#pragma unroll
        for (int k = 0; k < 8; k++) {
            *reinterpret_cast<float4*>(&ra[0]) = *reinterpret_cast<const float4*>(&As[k][ty * 4]);
            *reinterpret_cast<float4*>(&ra[4]) = *reinterpret_cast<const float4*>(&As[k][64 + ty * 4]);
            *reinterpret_cast<float4*>(&rb[0]) = *reinterpret_cast<const float4*>(&Bs[k][tx * 4]);
            *reinterpret_cast<float4*>(&rb[4]) = *reinterpret_cast<const float4*>(&Bs[k][64 + tx * 4]);
#pragma unroll
            for (int i = 0; i < 8; i++)
#pragma unroll
                for (int j = 0; j < 8; j++)
                    acc[i][j] = fmaf(ra[i], rb[j], acc[i][j]);
        }
        __syncthreads();
    }

#pragma unroll
    for (int i = 0; i < 8; i++) {
        int r = (i < 4) ? (ty * 4 + i) : (64 + ty * 4 + (i - 4));
        float* Crow = C + (size_t)(bm * 128 + r) * N + (size_t)bn * 128;
#pragma unroll
        for (int j = 0; j < 8; j++) {
            int cc = (j < 4) ? (tx * 4 + j) : (64 + tx * 4 + (j - 4));
            Crow[cc] = acc[i][j] + bias[bn * 128 + cc];
        }
    }
}

// ---------------------------------------------------------------------------
// Persistent clustered recurrence, register-reuse version.
//
// Grid: 128 CTAs as 16 clusters of 8. Cluster cl handles batches [4cl,4cl+4).
// CTA rank r holds W_hh[:, r*64:(r+1)*64) in smem as sW[c][k] (row stride 516).
//
// Compute phase: thread (c2 = tid&31, kq = tid>>5) owns columns {c2, c2+32}
// and k-range [64*kq, 64*kq+64), accumulating partials for ALL 4 batch rows
// in registers (each W value loaded from smem once, used 4x). Partials go to
// sRed[kq][nb][col]; after __syncthreads, thread (nb = tid>>6, c = tid&63)
// reduces 8 partials, applies tanh, broadcasts h into every cluster peer via
// st.shared::cluster, stores g_hs, then one cluster.sync per step.
// ---------------------------------------------------------------------------
__device__ __forceinline__ void cluster_sync_all()
{
    asm volatile("barrier.cluster.arrive.aligned;\n\t"
                 "barrier.cluster.wait.aligned;" ::: "memory");
}

extern __shared__ float s_dyn[];

__global__ void __cluster_dims__(CLUSTER_SZ, 1, 1) __launch_bounds__(256, 1)
rnn_recurrence(const float* __restrict__ W_hh)
{
    float* sW   = s_dyn;                                   // [64][516]
    float* sh   = sW + COLS_PER_CTA * SWS;                 // [2][4][512]
    float* sRed = sh + 2 * NB_PER_CL * HID;                // [8][4][64]

    const int tid  = threadIdx.x;
    const int rank = blockIdx.x & (CLUSTER_SZ - 1);
    const int cl   = blockIdx.x / CLUSTER_SZ;
    const int col0 = rank * COLS_PER_CTA;

    // Compute-phase mapping
    const int c2 = tid & 31;         // column pair base (cols c2, c2+32)
    const int kq = tid >> 5;         // k-group 0..7

    // Reduce-phase mapping
    const int rnb  = tid >> 6;               // 0..3
    const int rc   = tid & 63;               // 0..63
    const int rcol = col0 + rc;
    const int rgb  = cl * NB_PER_CL + rnb;   // global batch row

    // Load W slice: sW[c][k] = W_hh[k][col0 + c]
    for (int idx = tid; idx < COLS_PER_CTA * HID; idx += 256) {
        int c = idx & 63;
        int k = idx >> 6;
        sW[c * SWS + k] = W_hh[(size_t)k * HID + col0 + c];
    }
    // Zero h buffer 0 (h_{-1} = 0)
    for (int i = tid; i < 2 * NB_PER_CL * HID; i += 256) sh[i] = 0.f;
    __syncthreads();
    cluster_sync_all();   // all peers initialized before any remote stores

    uint32_t sh_u32;
    asm("{ .reg .u64 t; cvta.to.shared.u64 t, %1; cvt.u32.u64 %0, t; }"
        : "=r"(sh_u32) : "l"(sh));

    const float* w0_base = sW + c2 * SWS + kq * K_PER;
    const float* w1_base = w0_base + 32 * SWS;

    int p = 0;
    for (int t = 0; t < T_STEPS; t++) {
        // Prefetch the input-projection term for this step (consumed in the
        // reduce phase, ~2K cycles later — latency fully hidden).
        const float xh_v = g_xh[((size_t)rgb * T_STEPS + t) * HID + rcol];

        // ---- compute phase: partial dot products, 4 batches in registers ----
        const float4* w0 = reinterpret_cast<const float4*>(w0_base);
        const float4* w1 = reinterpret_cast<const float4*>(w1_base);
        const float4* hb = reinterpret_cast<const float4*>(sh + p * NB_PER_CL * HID
                                                           + kq * K_PER);
        // accumulators [col 0/1][nb]
        float a00 = 0.f, a01 = 0.f, a02 = 0.f, a03 = 0.f;
        float a10 = 0.f, a11 = 0.f, a12 = 0.f, a13 = 0.f;

#pragma unroll 8
        for (int j = 0; j < K_PER / 4; j++) {
            float4 wv0 = w0[j];
            float4 wv1 = w1[j];
            float4 h0 = hb[j];                       // nb=0 (broadcast)
            float4 h1 = hb[(HID / 4) + j];           // nb=1
            float4 h2 = hb[2 * (HID / 4) + j];       // nb=2
            float4 h3 = hb[3 * (HID / 4) + j];       // nb=3

            a00 = fmaf(wv0.x, h0.x, a00); a00 = fmaf(wv0.y, h0.y, a00);
            a00 = fmaf(wv0.z, h0.z, a00); a00 = fmaf(wv0.w, h0.w, a00);
            a01 = fmaf(wv0.x, h1.x, a01); a01 = fmaf(wv0.y, h1.y, a01);
            a01 = fmaf(wv0.z, h1.z, a01); a01 = fmaf(wv0.w, h1.w, a01);
            a02 = fmaf(wv0.x, h2.x, a02); a02 = fmaf(wv0.y, h2.y, a02);
            a02 = fmaf(wv0.z, h2.z, a02); a02 = fmaf(wv0.w, h2.w, a02);
            a03 = fmaf(wv0.x, h3.x, a03); a03 = fmaf(wv0.y, h3.y, a03);
            a03 = fmaf(wv0.z, h3.z, a03); a03 = fmaf(wv0.w, h3.w, a03);

            a10 = fmaf(wv1.x, h0.x, a10); a10 = fmaf(wv1.y, h0.y, a10);
            a10 = fmaf(wv1.z, h0.z, a10); a10 = fmaf(wv1.w, h0.w, a10);
            a11 = fmaf(wv1.x, h1.x, a11); a11 = fmaf(wv1.y, h1.y, a11);
            a11 = fmaf(wv1.z, h1.z, a11); a11 = fmaf(wv1.w, h1.w, a11);
            a12 = fmaf(wv1.x, h2.x, a12); a12 = fmaf(wv1.y, h2.y, a12);
            a12 = fmaf(wv1.z, h2.z, a12); a12 = fmaf(wv1.w, h2.w, a12);
            a13 = fmaf(wv1.x, h3.x, a13); a13 = fmaf(wv1.y, h3.y, a13);
            a13 = fmaf(wv1.z, h3.z, a13); a13 = fmaf(wv1.w, h3.w, a13);
        }

        // sRed[kq][nb][col]
        {
            float* r0 = sRed + (kq * NB_PER_CL) * COLS_PER_CTA + c2;
            r0[0 * COLS_PER_CTA]      = a00;
            r0[1 * COLS_PER_CTA]      = a01;
            r0[2 * COLS_PER_CTA]      = a02;
            r0[3 * COLS_PER_CTA]      = a03;
            r0[0 * COLS_PER_CTA + 32] = a10;
            r0[1 * COLS_PER_CTA + 32] = a11;
            r0[2 * COLS_PER_CTA + 32] = a12;
            r0[3 * COLS_PER_CTA + 32] = a13;
        }
        __syncthreads();

        // ---- reduce phase: thread (rnb, rc) ----
        {
            const float* rr = sRed + rnb * COLS_PER_CTA + rc;
            float s = 0.f;
#pragma unroll
            for (int q = 0; q < KQ_GROUPS; q++)
                s += rr[q * NB_PER_CL * COLS_PER_CTA];

            const float val = tanhf(s + xh_v);

            // Broadcast into h[1-p] of every CTA in the cluster (incl. self).
            const uint32_t dst = sh_u32 +
                (uint32_t)((((1 - p) * NB_PER_CL + rnb) * HID + rcol) * sizeof(float));
#pragma unroll
            for (int r = 0; r < CLUSTER_SZ; r++) {
                uint32_t raddr;
                asm volatile("mapa.shared::cluster.u32 %0, %1, %2;"
                             : "=r"(raddr) : "r"(dst), "r"(r));
                asm volatile("st.shared::cluster.f32 [%0], %1;"
                             :: "r"(raddr), "f"(val) : "memory");
            }

            // Persist h_t for the output GEMM.
            g_hs[((size_t)rgb * T_STEPS + t) * HID + rcol] = val;
        }

        cluster_sync_all();   // release our stores, acquire peers' stores
        p ^= 1;               // also orders sRed reuse for the next step
    }
}

// ---------------------------------------------------------------------------
// Launch
// ---------------------------------------------------------------------------
extern "C" void kernel_launch(void* const* d_in, const int* in_sizes, int n_in,
                              void* d_out, int out_size)
{
    (void)in_sizes; (void)n_in; (void)out_size;
    const float* x    = (const float*)d_in[0];
    const float* W_xh = (const float*)d_in[1];
    const float* W_hh = (const float*)d_in[2];
    const float* b_h  = (const float*)d_in[3];
    const float* W_hy = (const float*)d_in[4];
    const float* b_y  = (const float*)d_in[5];
    float* out = (float*)d_out;

    float *xh_ptr = nullptr, *hs_ptr = nullptr;
    cudaGetSymbolAddress((void**)&xh_ptr, g_xh);
    cudaGetSymbolAddress((void**)&hs_ptr, g_hs);

    const int M = BATCH * T_STEPS;   // 65536

    // 1) xh = x @ W_xh + b_h        [65536,256]@[256,512]
    {
        dim3 grid(HID / 128, M / 128);
        sgemm_bias<<<grid, 256>>>(x, W_xh, b_h, xh_ptr, M, HID, IN_DIM);
    }

    // 2) recurrence (persistent, 16 clusters x 8 CTAs)
    {
        size_t smem = (size_t)(COLS_PER_CTA * SWS + 2 * NB_PER_CL * HID
                               + KQ_GROUPS * NB_PER_CL * COLS_PER_CTA) * sizeof(float);
        cudaFuncSetAttribute(rnn_recurrence,
                             cudaFuncAttributeMaxDynamicSharedMemorySize, (int)smem);
        rnn_recurrence<<<(BATCH / NB_PER_CL) * CLUSTER_SZ, 256, smem>>>(W_hh);
    }

    // 3) out = hs @ W_hy + b_y      [65536,512]@[512,256]
    {
        dim3 grid(OUT_DIM / 128, M / 128);
        sgemm_bias<<<grid, 256>>>(hs_ptr, W_hy, b_y, out, M, OUT_DIM, HID);
    }
}

// round 9
// speedup vs baseline: 1.7462x; 1.0635x over previous
#include <cuda_runtime.h>
#include <cstdint>
#include <cstddef>

// Problem dims (fixed by the dataset)
#define T_STEPS 1024
#define BATCH   64
#define HID     512
#define IN_DIM  256
#define OUT_DIM 256

// Recurrence tiling
#define CLUSTER_SZ 8          // CTAs per cluster
#define COLS_PER_CTA 64       // 512 / 8
#define NB_PER_CL 4           // batch rows per cluster (16 clusters * 4 = 64)
#define SWS 516               // padded row stride (floats) for W slice in smem
#define THREADS_R 512         // 16 warps -> 4 warps/SMSP (latency hiding)
#define KQ_GROUPS 16          // k-dimension split per CTA
#define K_PER (HID / KQ_GROUPS)   // 32 k-values per compute thread

// Scratch (device globals are the sanctioned scratch mechanism)
__device__ float g_xh[(size_t)BATCH * T_STEPS * HID];   // 128 MiB
__device__ float g_hs[(size_t)BATCH * T_STEPS * HID];   // 128 MiB

// ---------------------------------------------------------------------------
// Classic 128x128x8 fp32 SGEMM with bias:  C[M,N] = A[M,K] @ B[K,N] + bias[N]
// ---------------------------------------------------------------------------
__global__ __launch_bounds__(256)
void sgemm_bias(const float* __restrict__ A, const float* __restrict__ B,
                const float* __restrict__ bias, float* __restrict__ C,
                int M, int N, int K)
{
    __shared__ float As[8][128];
    __shared__ float Bs[8][128];

    const int tid = threadIdx.x;
    const int bm = blockIdx.y;
    const int bn = blockIdx.x;

    const float* Ablk = A + (size_t)bm * 128 * K;
    const float* Bblk = B + (size_t)bn * 128;

    const int arow = tid >> 1;
    const int acol = (tid & 1) * 4;
    const int brow = tid >> 5;
    const int bcol = (tid & 31) * 4;

    const int tx = tid & 15;
    const int ty = tid >> 4;

    float acc[8][8];
#pragma unroll
    for (int i = 0; i < 8; i++)
#pragma unroll
        for (int j = 0; j < 8; j++) acc[i][j] = 0.f;

    float ra[8], rb[8];

    for (int k0 = 0; k0 < K; k0 += 8) {
        float4 av = *reinterpret_cast<const float4*>(Ablk + (size_t)arow * K + k0 + acol);
        float4 bv = *reinterpret_cast<const float4*>(Bblk + (size_t)(k0 + brow) * N + bcol);
        As[acol + 0][arow] = av.x;
        As[acol + 1][arow] = av.y;
        As[acol + 2][arow] = av.z;
        As[acol + 3][arow] = av.w;
        *reinterpret_cast<float4*>(&Bs[brow][bcol]) = bv;
        __syncthreads();

#pragma unroll
        for (int k = 0; k < 8; k++) {
            *reinterpret_cast<float4*>(&ra[0]) = *reinterpret_cast<const float4*>(&As[k][ty * 4]);
            *reinterpret_cast<float4*>(&ra[4]) = *reinterpret_cast<const float4*>(&As[k][64 + ty * 4]);
            *reinterpret_cast<float4*>(&rb[0]) = *reinterpret_cast<const float4*>(&Bs[k][tx * 4]);
            *reinterpret_cast<float4*>(&rb[4]) = *reinterpret_cast<const float4*>(&Bs[k][64 + tx * 4]);
#pragma unroll
            for (int i = 0; i < 8; i++)
#pragma unroll
                for (int j = 0; j < 8; j++)
                    acc[i][j] = fmaf(ra[i], rb[j], acc[i][j]);
        }
        __syncthreads();
    }

#pragma unroll
    for (int i = 0; i < 8; i++) {
        int r = (i < 4) ? (ty * 4 + i) : (64 + ty * 4 + (i - 4));
        float* Crow = C + (size_t)(bm * 128 + r) * N + (size_t)bn * 128;
#pragma unroll
        for (int j = 0; j < 8; j++) {
            int cc = (j < 4) ? (tx * 4 + j) : (64 + tx * 4 + (j - 4));
            Crow[cc] = acc[i][j] + bias[bn * 128 + cc];
        }
    }
}

// ---------------------------------------------------------------------------
// Persistent clustered recurrence, v3: 512 threads, batch-innermost h layout.
//
// Grid: 128 CTAs as 16 clusters of 8. Cluster cl handles batches [4cl,4cl+4).
// CTA rank r holds W_hh[:, r*64:(r+1)*64) in smem as sW[c][k] (row stride 516).
//
// h buffer layout: sh[2][512][4]  -- hbuf[p][gcol][nb], batch innermost, so
//   * compute reads one broadcast LDS.128 = all 4 batches of one k
//   * one thread owns a column's 4 batch outputs -> 16B v4 remote stores
//
// Compute phase: thread (c2 = tid&31, kq = tid>>5 in [0,16)) owns columns
// {c2, c2+32} and k-range [32*kq, 32*kq+32), accumulating 2x4 partials in
// registers. Partials -> sRed[nb][kq][c] (conflict-free scalar STS).
// Reduce phase: threads 0..63 (thread = local column c) sum 16 partials per
// batch, tanh, then one st.shared::cluster.v4 per cluster peer + g_hs store.
// One cluster.sync per step publishes h to all peers.
// ---------------------------------------------------------------------------
__device__ __forceinline__ void cluster_sync_all()
{
    asm volatile("barrier.cluster.arrive.aligned;\n\t"
                 "barrier.cluster.wait.aligned;" ::: "memory");
}

extern __shared__ float s_dyn[];

__global__ void __cluster_dims__(CLUSTER_SZ, 1, 1) __launch_bounds__(THREADS_R, 1)
rnn_recurrence(const float* __restrict__ W_hh)
{
    float* sW   = s_dyn;                                   // [64][516]
    float* sh   = sW + COLS_PER_CTA * SWS;                 // [2][512][4]
    float* sRed = sh + 2 * HID * NB_PER_CL;                // [4][16][64]

    const int tid  = threadIdx.x;
    const int rank = blockIdx.x & (CLUSTER_SZ - 1);
    const int cl   = blockIdx.x / CLUSTER_SZ;
    const int col0 = rank * COLS_PER_CTA;

    // Compute-phase mapping
    const int c2 = tid & 31;         // column pair base (cols c2, c2+32)
    const int kq = tid >> 5;         // k-group 0..15

    // Reduce-phase mapping (threads 0..63): local column = tid
    const int rcol = col0 + tid;               // global column (tid<64 only)
    const int gb0  = cl * NB_PER_CL;           // first batch row of cluster

    // Load W slice: sW[c][k] = W_hh[k][col0 + c]
    for (int idx = tid; idx < COLS_PER_CTA * HID; idx += THREADS_R) {
        int c = idx & 63;
        int k = idx >> 6;
        sW[c * SWS + k] = W_hh[(size_t)k * HID + col0 + c];
    }
    // Zero both h buffers (h_{-1} = 0)
    for (int i = tid; i < 2 * HID * NB_PER_CL; i += THREADS_R) sh[i] = 0.f;
    __syncthreads();
    cluster_sync_all();   // all peers initialized before any remote stores

    uint32_t sh_u32;
    asm("{ .reg .u64 t; cvta.to.shared.u64 t, %1; cvt.u32.u64 %0, t; }"
        : "=r"(sh_u32) : "l"(sh));

    const float4* w0_base = reinterpret_cast<const float4*>(sW + c2 * SWS + kq * K_PER);
    const float4* w1_base = reinterpret_cast<const float4*>(sW + (c2 + 32) * SWS + kq * K_PER);

    int p = 0;
    for (int t = 0; t < T_STEPS; t++) {
        // Prefetch input-projection terms (reduce threads only; consumed
        // ~2K cycles later, latency fully hidden).
        float xh0 = 0.f, xh1 = 0.f, xh2 = 0.f, xh3 = 0.f;
        if (tid < COLS_PER_CTA) {
            const size_t base = (size_t)t * HID + rcol;
            xh0 = g_xh[((size_t)(gb0 + 0) * T_STEPS) * HID + base];
            xh1 = g_xh[((size_t)(gb0 + 1) * T_STEPS) * HID + base];
            xh2 = g_xh[((size_t)(gb0 + 2) * T_STEPS) * HID + base];
            xh3 = g_xh[((size_t)(gb0 + 3) * T_STEPS) * HID + base];
        }

        // ---- compute phase ----
        // hb4[k] = float4 of 4 batches at hidden index k (broadcast loads)
        const float4* hb4 = reinterpret_cast<const float4*>(sh + p * HID * NB_PER_CL)
                            + kq * K_PER;

        float a00 = 0.f, a01 = 0.f, a02 = 0.f, a03 = 0.f;   // col c2
        float a10 = 0.f, a11 = 0.f, a12 = 0.f, a13 = 0.f;   // col c2+32

#pragma unroll
        for (int j = 0; j < K_PER / 4; j++) {
            float4 wv0 = w0_base[j];
            float4 wv1 = w1_base[j];
            float4 h0 = hb4[4 * j + 0];   // batches of k = kq*32+4j
            float4 h1 = hb4[4 * j + 1];
            float4 h2 = hb4[4 * j + 2];
            float4 h3 = hb4[4 * j + 3];

            a00 = fmaf(wv0.x, h0.x, a00); a01 = fmaf(wv0.x, h0.y, a01);
            a02 = fmaf(wv0.x, h0.z, a02); a03 = fmaf(wv0.x, h0.w, a03);
            a10 = fmaf(wv1.x, h0.x, a10); a11 = fmaf(wv1.x, h0.y, a11);
            a12 = fmaf(wv1.x, h0.z, a12); a13 = fmaf(wv1.x, h0.w, a13);

            a00 = fmaf(wv0.y, h1.x, a00); a01 = fmaf(wv0.y, h1.y, a01);
            a02 = fmaf(wv0.y, h1.z, a02); a03 = fmaf(wv0.y, h1.w, a03);
            a10 = fmaf(wv1.y, h1.x, a10); a11 = fmaf(wv1.y, h1.y, a11);
            a12 = fmaf(wv1.y, h1.z, a12); a13 = fmaf(wv1.y, h1.w, a13);

            a00 = fmaf(wv0.z, h2.x, a00); a01 = fmaf(wv0.z, h2.y, a01);
            a02 = fmaf(wv0.z, h2.z, a02); a03 = fmaf(wv0.z, h2.w, a03);
            a10 = fmaf(wv1.z, h2.x, a10); a11 = fmaf(wv1.z, h2.y, a11);
            a12 = fmaf(wv1.z, h2.z, a12); a13 = fmaf(wv1.z, h2.w, a13);

            a00 = fmaf(wv0.w, h3.x, a00); a01 = fmaf(wv0.w, h3.y, a01);
            a02 = fmaf(wv0.w, h3.z, a02); a03 = fmaf(wv0.w, h3.w, a03);
            a10 = fmaf(wv1.w, h3.x, a10); a11 = fmaf(wv1.w, h3.y, a11);
            a12 = fmaf(wv1.w, h3.z, a12); a13 = fmaf(wv1.w, h3.w, a13);
        }

        // Partials -> sRed[nb][kq][c]  (scalar stores, conflict-free: bank=c)
        {
            float* r0 = sRed + kq * COLS_PER_CTA + c2;
            r0[0 * KQ_GROUPS * COLS_PER_CTA]      = a00;
            r0[1 * KQ_GROUPS * COLS_PER_CTA]      = a01;
            r0[2 * KQ_GROUPS * COLS_PER_CTA]      = a02;
            r0[3 * KQ_GROUPS * COLS_PER_CTA]      = a03;
            r0[0 * KQ_GROUPS * COLS_PER_CTA + 32] = a10;
            r0[1 * KQ_GROUPS * COLS_PER_CTA + 32] = a11;
            r0[2 * KQ_GROUPS * COLS_PER_CTA + 32] = a12;
            r0[3 * KQ_GROUPS * COLS_PER_CTA + 32] = a13;
        }
        __syncthreads();

        // ---- reduce phase: threads 0..63, one column each, all 4 batches ----
        if (tid < COLS_PER_CTA) {
            float s0 = 0.f, s1 = 0.f, s2 = 0.f, s3 = 0.f;
            const float* rr = sRed + tid;
#pragma unroll
            for (int q = 0; q < KQ_GROUPS; q++) {
                s0 += rr[(0 * KQ_GROUPS + q) * COLS_PER_CTA];
                s1 += rr[(1 * KQ_GROUPS + q) * COLS_PER_CTA];
                s2 += rr[(2 * KQ_GROUPS + q) * COLS_PER_CTA];
                s3 += rr[(3 * KQ_GROUPS + q) * COLS_PER_CTA];
            }
            const float v0 = tanhf(s0 + xh0);
            const float v1 = tanhf(s1 + xh1);
            const float v2 = tanhf(s2 + xh2);
            const float v3 = tanhf(s3 + xh3);

            // Broadcast 16B (4 batches of this column) into h[1-p] of every
            // CTA in the cluster (incl. self).
            const uint32_t dst = sh_u32 +
                (uint32_t)(((1 - p) * HID + rcol) * NB_PER_CL * sizeof(float));
#pragma unroll
            for (int r = 0; r < CLUSTER_SZ; r++) {
                uint32_t raddr;
                asm volatile("mapa.shared::cluster.u32 %0, %1, %2;"
                             : "=r"(raddr) : "r"(dst), "r"(r));
                asm volatile("st.shared::cluster.v4.f32 [%0], {%1, %2, %3, %4};"
                             :: "r"(raddr), "f"(v0), "f"(v1), "f"(v2), "f"(v3)
                             : "memory");
            }

            // Persist h_t for the output GEMM (fire-and-forget).
            const size_t base = (size_t)t * HID + rcol;
            g_hs[((size_t)(gb0 + 0) * T_STEPS) * HID + base] = v0;
            g_hs[((size_t)(gb0 + 1) * T_STEPS) * HID + base] = v1;
            g_hs[((size_t)(gb0 + 2) * T_STEPS) * HID + base] = v2;
            g_hs[((size_t)(gb0 + 3) * T_STEPS) * HID + base] = v3;
        }

        cluster_sync_all();   // release our stores, acquire peers' stores;
                              // also orders sRed reuse for the next step
        p ^= 1;
    }
}

// ---------------------------------------------------------------------------
// Launch
// ---------------------------------------------------------------------------
extern "C" void kernel_launch(void* const* d_in, const int* in_sizes, int n_in,
                              void* d_out, int out_size)
{
    (void)in_sizes; (void)n_in; (void)out_size;
    const float* x    = (const float*)d_in[0];
    const float* W_xh = (const float*)d_in[1];
    const float* W_hh = (const float*)d_in[2];
    const float* b_h  = (const float*)d_in[3];
    const float* W_hy = (const float*)d_in[4];
    const float* b_y  = (const float*)d_in[5];
    float* out = (float*)d_out;

    float *xh_ptr = nullptr, *hs_ptr = nullptr;
    cudaGetSymbolAddress((void**)&xh_ptr, g_xh);
    cudaGetSymbolAddress((void**)&hs_ptr, g_hs);

    const int M = BATCH * T_STEPS;   // 65536

    // 1) xh = x @ W_xh + b_h        [65536,256]@[256,512]
    {
        dim3 grid(HID / 128, M / 128);
        sgemm_bias<<<grid, 256>>>(x, W_xh, b_h, xh_ptr, M, HID, IN_DIM);
    }

    // 2) recurrence (persistent, 16 clusters x 8 CTAs)
    {
        size_t smem = (size_t)(COLS_PER_CTA * SWS + 2 * HID * NB_PER_CL
                               + NB_PER_CL * KQ_GROUPS * COLS_PER_CTA) * sizeof(float);
        cudaFuncSetAttribute(rnn_recurrence,
                             cudaFuncAttributeMaxDynamicSharedMemorySize, (int)smem);
        rnn_recurrence<<<(BATCH / NB_PER_CL) * CLUSTER_SZ, THREADS_R, smem>>>(W_hh);
    }

    // 3) out = hs @ W_hy + b_y      [65536,512]@[512,256]
    {
        dim3 grid(OUT_DIM / 128, M / 128);
        sgemm_bias<<<grid, 256>>>(hs_ptr, W_hy, b_y, out, M, OUT_DIM, HID);
    }
}